// round 14
// baseline (speedup 1.0000x reference)
#include <cuda_runtime.h>
#include <cstdint>
#include <cstdio>

#define NMAX   100000
#define EMAX   1200000
#define INF    128
#define HID    64
#define OUTF   40

// ---------------- scratch (device globals) ---------------------------------
__device__ int   g_degi  [NMAX];
__device__ int   g_start [NMAX];
__device__ int   g_cursor[NMAX];
__device__ int   g_part  [128];
__device__ int   g_poff  [128];
__device__ float g_dinv  [NMAX];
__device__ int2  g_edge  [EMAX];        // {src, float_bits(weight)}
__device__ float g_h0    [(size_t)NMAX * HID];
__device__ float g_h1    [(size_t)NMAX * HID];
__device__ float g_t     [(size_t)NMAX * HID];
__device__ float g_emb   [(size_t)NMAX * HID];
__device__ int   g_idx64;

__device__ __forceinline__ uint32_t f2tf32(float x) {
    uint32_t r;
    asm("{ .reg .b32 t; cvt.rna.tf32.f32 t, %1; mov.b32 %0, t; }" : "=r"(r) : "f"(x));
    return r;
}
// split x into tf32 hi + tf32 lo (3xTF32 decomposition)
__device__ __forceinline__ void tf32_split(float x, uint32_t& hi, uint32_t& lo) {
    hi = f2tf32(x);
    lo = f2tf32(x - __uint_as_float(hi));
}

// ---------------- init: zero degree + dtype sniff --------------------------
__global__ void k_init(const unsigned int* __restrict__ w, int n) {
    int i = blockIdx.x * blockDim.x + threadIdx.x;
    if (i < n) g_degi[i] = 0;
    if (blockIdx.x == 0) {
        int t = threadIdx.x;
        int nz = 0;
#pragma unroll
        for (int k = 0; k < 8; k++) nz |= (w[2 * (t * 8 + k) + 1] != 0u);
        int any = __syncthreads_or(nz);
        if (t == 0) g_idx64 = (any == 0) ? 1 : 0;
    }
}

__device__ __forceinline__ void load_edge(const void* eidx, int E, int e, int& s, int& d) {
    if (g_idx64) {
        const long long* p = (const long long*)eidx;
        s = (int)p[e];
        d = (int)p[(size_t)E + e];
    } else {
        const int* p = (const int*)eidx;
        s = p[e];
        d = p[(size_t)E + e];
    }
}

__global__ void k_deg(const void* __restrict__ eidx, int E) {
    int e = blockIdx.x * blockDim.x + threadIdx.x;
    if (e >= E) return;
    int s, d;
    load_edge(eidx, E, e, s, d);
    atomicAdd(&g_degi[d], 1);
}

// ---------------- 2-level exclusive scan of g_degi -------------------------
__global__ void k_scan1(int n) {
    __shared__ int sm[256];
    int t = threadIdx.x;
    int base = blockIdx.x * 1024 + t * 4;
    int s = 0;
#pragma unroll
    for (int j = 0; j < 4; j++) {
        int i = base + j;
        if (i < n) s += g_degi[i];
    }
    sm[t] = s;
    __syncthreads();
    for (int off = 128; off > 0; off >>= 1) {
        if (t < off) sm[t] += sm[t + off];
        __syncthreads();
    }
    if (t == 0) g_part[blockIdx.x] = sm[0];
}

__global__ void k_scan2(int nblk) {
    __shared__ int sm[128];
    int t = threadIdx.x;
    sm[t] = (t < nblk) ? g_part[t] : 0;
    __syncthreads();
    if (t == 0) {
        int acc = 0;
        for (int i = 0; i < nblk; i++) {
            int v = sm[i];
            sm[i] = acc;
            acc += v;
        }
    }
    __syncthreads();
    if (t < nblk) g_poff[t] = sm[t];
}

__global__ void k_scan3(int n) {
    __shared__ int sm[256];
    int t = threadIdx.x;
    int base = blockIdx.x * 1024 + t * 4;
    int d[4];
    int s = 0;
#pragma unroll
    for (int j = 0; j < 4; j++) {
        int i = base + j;
        d[j] = (i < n) ? g_degi[i] : 0;
        s += d[j];
    }
    sm[t] = s;
    __syncthreads();
    for (int off = 1; off < 256; off <<= 1) {
        int v = (t >= off) ? sm[t - off] : 0;
        __syncthreads();
        sm[t] += v;
        __syncthreads();
    }
    int excl = g_poff[blockIdx.x] + sm[t] - s;
#pragma unroll
    for (int j = 0; j < 4; j++) {
        int i = base + j;
        if (i < n) {
            g_start[i]  = excl;
            g_cursor[i] = excl;
            g_dinv[i]   = rsqrtf((float)d[j] + 1.0f);
        }
        excl += d[j];
    }
}

__global__ void k_place(const void* __restrict__ eidx, int E) {
    int e = blockIdx.x * blockDim.x + threadIdx.x;
    if (e >= E) return;
    int s, d;
    load_edge(eidx, E, e, s, d);
    int pos = atomicAdd(&g_cursor[d], 1);
    g_edge[pos] = make_int2(s, __float_as_int(g_dinv[s] * g_dinv[d]));
}

// ---------------- 3xTF32 mma.sync GEMM: [n,KDIM] @ [KDIM,64] -> C ----------
// BM=128, BN=64, 256 threads (8 warps, 4x2), warp tile 32x32.
// K chunked by 32; A staged hi/lo [128][36], B staged hi/lo [32][72].
// acc += Ahi*Bhi + Ahi*Blo + Alo*Bhi  (fp32-grade accuracy)
template <int KDIM, bool ACT>
__global__ void __launch_bounds__(256) k_mma(const float* __restrict__ A,
                                             const float* __restrict__ W,
                                             const float* __restrict__ actb,
                                             float* __restrict__ C, int n) {
    __shared__ uint32_t sAh[128 * 36];   // 18 KB
    __shared__ uint32_t sAl[128 * 36];   // 18 KB
    __shared__ uint32_t sBh[32 * 72];    // 9 KB
    __shared__ uint32_t sBl[32 * 72];    // 9 KB

    const int tid  = threadIdx.x;
    const int wid  = tid >> 5;
    const int lane = tid & 31;
    const int wm   = wid >> 1;           // 0..3: M subtile (32 rows)
    const int wn   = wid & 1;            // 0..1: N subtile (32 cols)
    const int gr   = lane >> 2;          // 0..7
    const int gc   = lane & 3;           // 0..3
    const int rowBase = blockIdx.x * 128;

    float acc[2][4][4];
#pragma unroll
    for (int i = 0; i < 2; i++)
#pragma unroll
        for (int j = 0; j < 4; j++)
#pragma unroll
            for (int r = 0; r < 4; r++) acc[i][j][r] = 0.f;

    constexpr int NCH = KDIM / 32;
    for (int c = 0; c < NCH; c++) {
        const int k0 = c * 32;
        // stage A chunk: 128 rows x 32 cols, hi/lo split
#pragma unroll
        for (int it = 0; it < 4; it++) {
            int i   = tid + it * 256;
            int row = i >> 3, c4 = i & 7;
            float4 v = make_float4(0.f, 0.f, 0.f, 0.f);
            if (rowBase + row < n) {
                v = *(const float4*)&A[(size_t)(rowBase + row) * KDIM + k0 + c4 * 4];
                if (ACT) {
                    float4 b = *(const float4*)&actb[k0 + c4 * 4];
                    v.x = fmaxf(v.x + b.x, 0.f);
                    v.y = fmaxf(v.y + b.y, 0.f);
                    v.z = fmaxf(v.z + b.z, 0.f);
                    v.w = fmaxf(v.w + b.w, 0.f);
                }
            }
            uint32_t* ph = &sAh[row * 36 + c4 * 4];
            uint32_t* pl = &sAl[row * 36 + c4 * 4];
            tf32_split(v.x, ph[0], pl[0]);
            tf32_split(v.y, ph[1], pl[1]);
            tf32_split(v.z, ph[2], pl[2]);
            tf32_split(v.w, ph[3], pl[3]);
        }
        // stage B chunk: B[k][nn] = W[(k0+k)*64 + nn], hi/lo split
#pragma unroll
        for (int it = 0; it < 2; it++) {
            int i  = tid + it * 256;
            int kk = i >> 4, n4 = i & 15;
            float4 v = *(const float4*)&W[(size_t)(k0 + kk) * 64 + n4 * 4];
            uint32_t* ph = &sBh[kk * 72 + n4 * 4];
            uint32_t* pl = &sBl[kk * 72 + n4 * 4];
            tf32_split(v.x, ph[0], pl[0]);
            tf32_split(v.y, ph[1], pl[1]);
            tf32_split(v.z, ph[2], pl[2]);
            tf32_split(v.w, ph[3], pl[3]);
        }
        __syncthreads();

#pragma unroll
        for (int ks = 0; ks < 4; ks++) {
            const int kk = ks * 8;
            uint32_t afh[2][4], afl[2][4];
#pragma unroll
            for (int mi = 0; mi < 2; mi++) {
                int r0 = wm * 32 + mi * 16 + gr;
                afh[mi][0] = sAh[(r0    ) * 36 + kk + gc    ];
                afh[mi][1] = sAh[(r0 + 8) * 36 + kk + gc    ];
                afh[mi][2] = sAh[(r0    ) * 36 + kk + gc + 4];
                afh[mi][3] = sAh[(r0 + 8) * 36 + kk + gc + 4];
                afl[mi][0] = sAl[(r0    ) * 36 + kk + gc    ];
                afl[mi][1] = sAl[(r0 + 8) * 36 + kk + gc    ];
                afl[mi][2] = sAl[(r0    ) * 36 + kk + gc + 4];
                afl[mi][3] = sAl[(r0 + 8) * 36 + kk + gc + 4];
            }
#pragma unroll
            for (int ni = 0; ni < 4; ni++) {
                int ncol = wn * 32 + ni * 8 + gr;
                uint32_t b0h = sBh[(kk + gc    ) * 72 + ncol];
                uint32_t b1h = sBh[(kk + gc + 4) * 72 + ncol];
                uint32_t b0l = sBl[(kk + gc    ) * 72 + ncol];
                uint32_t b1l = sBl[(kk + gc + 4) * 72 + ncol];
#pragma unroll
                for (int mi = 0; mi < 2; mi++) {
                    // lo terms first, hi*hi last
                    asm volatile(
                        "mma.sync.aligned.m16n8k8.row.col.f32.tf32.tf32.f32 "
                        "{%0,%1,%2,%3}, {%4,%5,%6,%7}, {%8,%9}, {%0,%1,%2,%3};"
                        : "+f"(acc[mi][ni][0]), "+f"(acc[mi][ni][1]),
                          "+f"(acc[mi][ni][2]), "+f"(acc[mi][ni][3])
                        : "r"(afh[mi][0]), "r"(afh[mi][1]), "r"(afh[mi][2]), "r"(afh[mi][3]),
                          "r"(b0l), "r"(b1l));
                    asm volatile(
                        "mma.sync.aligned.m16n8k8.row.col.f32.tf32.tf32.f32 "
                        "{%0,%1,%2,%3}, {%4,%5,%6,%7}, {%8,%9}, {%0,%1,%2,%3};"
                        : "+f"(acc[mi][ni][0]), "+f"(acc[mi][ni][1]),
                          "+f"(acc[mi][ni][2]), "+f"(acc[mi][ni][3])
                        : "r"(afl[mi][0]), "r"(afl[mi][1]), "r"(afl[mi][2]), "r"(afl[mi][3]),
                          "r"(b0h), "r"(b1h));
                    asm volatile(
                        "mma.sync.aligned.m16n8k8.row.col.f32.tf32.tf32.f32 "
                        "{%0,%1,%2,%3}, {%4,%5,%6,%7}, {%8,%9}, {%0,%1,%2,%3};"
                        : "+f"(acc[mi][ni][0]), "+f"(acc[mi][ni][1]),
                          "+f"(acc[mi][ni][2]), "+f"(acc[mi][ni][3])
                        : "r"(afh[mi][0]), "r"(afh[mi][1]), "r"(afh[mi][2]), "r"(afh[mi][3]),
                          "r"(b0h), "r"(b1h));
                }
            }
        }
        __syncthreads();
    }

#pragma unroll
    for (int mi = 0; mi < 2; mi++) {
#pragma unroll
        for (int ni = 0; ni < 4; ni++) {
            int r0 = rowBase + wm * 32 + mi * 16 + gr;
            int cc = wn * 32 + ni * 8 + gc * 2;
            if (r0 < n)
                *(float2*)&C[(size_t)r0 * 64 + cc] = make_float2(acc[mi][ni][0], acc[mi][ni][1]);
            if (r0 + 8 < n)
                *(float2*)&C[(size_t)(r0 + 8) * 64 + cc] = make_float2(acc[mi][ni][2], acc[mi][ni][3]);
        }
    }
}

// ---------------- CSR gather aggregation -----------------------------------
__global__ void k_gather(const float* __restrict__ src, float* __restrict__ dst, int n) {
    int node = blockIdx.x * 16 + (threadIdx.x >> 4);
    int lane = threadIdx.x & 15;
    if (node >= n) return;

    const float4* s4 = (const float4*)src;
    float di = g_dinv[node];
    float4 a = s4[(size_t)node * 16 + lane];
    float w0 = di * di;
    float4 acc = make_float4(a.x * w0, a.y * w0, a.z * w0, a.w * w0);

    int e   = g_start[node];
    int end = e + g_degi[node];

    for (; e + 4 <= end; e += 4) {
        int2 e0 = g_edge[e],     e1 = g_edge[e + 1];
        int2 e2 = g_edge[e + 2], e3 = g_edge[e + 3];
        float w0_ = __int_as_float(e0.y), w1_ = __int_as_float(e1.y);
        float w2_ = __int_as_float(e2.y), w3_ = __int_as_float(e3.y);
        float4 v0 = s4[(size_t)e0.x * 16 + lane];
        float4 v1 = s4[(size_t)e1.x * 16 + lane];
        float4 v2 = s4[(size_t)e2.x * 16 + lane];
        float4 v3 = s4[(size_t)e3.x * 16 + lane];
        acc.x += w0_ * v0.x + w1_ * v1.x + w2_ * v2.x + w3_ * v3.x;
        acc.y += w0_ * v0.y + w1_ * v1.y + w2_ * v2.y + w3_ * v3.y;
        acc.z += w0_ * v0.z + w1_ * v1.z + w2_ * v2.z + w3_ * v3.z;
        acc.w += w0_ * v0.w + w1_ * v1.w + w2_ * v2.w + w3_ * v3.w;
    }
    for (; e < end; e++) {
        int2 ee = g_edge[e];
        float w_ = __int_as_float(ee.y);
        float4 v0 = s4[(size_t)ee.x * 16 + lane];
        acc.x += w_ * v0.x; acc.y += w_ * v0.y; acc.z += w_ * v0.z; acc.w += w_ * v0.w;
    }
    ((float4*)dst)[(size_t)node * 16 + lane] = acc;
}

// ---------------- final head: emb+b2, logits, softmax, argmax --------------
__global__ void k_final(const float* __restrict__ Wc, const float* __restrict__ bc,
                        const float* __restrict__ b2,
                        float* __restrict__ out, int n) {
    __shared__ float Wcs[64][40];
    __shared__ float embs[64][65];
    __shared__ float lg[64][41];
    __shared__ float bcs[40];
    __shared__ float b2s[64];
    __shared__ float rsum[64];

    int tid  = threadIdx.x;
    int base = blockIdx.x * 64;

    for (int i = tid; i < 64 * 40; i += 256) Wcs[i / 40][i % 40] = Wc[i];
    if (tid < 40) bcs[tid] = bc[tid];
    if (tid < 64) b2s[tid] = b2[tid];
    __syncthreads();

    float* outL = out;
    float* outE = out + (size_t)n * 40;
    float* outS = out + (size_t)n * 104;
    float* outH = out + (size_t)n * 144;

    for (int i = tid; i < 64 * 64; i += 256) {
        int r = i >> 6, c = i & 63;
        int node = base + r;
        float v = 0.f;
        if (node < n) {
            v = g_emb[(size_t)node * 64 + c] + b2s[c];
            outE[(size_t)node * 64 + c] = v;
        }
        embs[r][c] = v;
    }
    __syncthreads();

    int tx = tid & 7, ty = tid >> 3;
    float acc[2][5];
#pragma unroll
    for (int i = 0; i < 2; i++)
#pragma unroll
        for (int j = 0; j < 5; j++) acc[i][j] = bcs[tx * 5 + j];
    for (int k = 0; k < 64; k++) {
        float a0 = embs[ty * 2 + 0][k];
        float a1 = embs[ty * 2 + 1][k];
#pragma unroll
        for (int j = 0; j < 5; j++) {
            float b = Wcs[k][tx * 5 + j];
            acc[0][j] += a0 * b;
            acc[1][j] += a1 * b;
        }
    }
#pragma unroll
    for (int i = 0; i < 2; i++)
#pragma unroll
        for (int j = 0; j < 5; j++) lg[ty * 2 + i][tx * 5 + j] = acc[i][j];
    __syncthreads();

    for (int i = tid; i < 64 * 40; i += 256) {
        int r = i / 40, c = i % 40;
        int node = base + r;
        if (node < n) outL[(size_t)node * 40 + c] = lg[r][c];
    }
    __syncthreads();

    if (tid < 64) {
        int node = base + tid;
        float m = -1e30f;
        int bi = 0;
#pragma unroll
        for (int j = 0; j < 40; j++) {
            float v = lg[tid][j];
            if (v > m) { m = v; bi = j; }
        }
        float s = 0.f;
#pragma unroll
        for (int j = 0; j < 40; j++) {
            float e = __expf(lg[tid][j] - m);
            lg[tid][j] = e;
            s += e;
        }
        rsum[tid] = 1.f / s;
        if (node < n) outH[node] = (float)bi;
    }
    __syncthreads();

    for (int i = tid; i < 64 * 40; i += 256) {
        int r = i / 40, c = i % 40;
        int node = base + r;
        if (node < n) outS[(size_t)node * 40 + c] = lg[r][c] * rsum[r];
    }
}

// ---------------- launch ----------------------------------------------------
extern "C" void kernel_launch(void* const* d_in, const int* in_sizes, int n_in,
                              void* d_out, int out_size) {
    const float* x  = (const float*)d_in[0];
    const void*  ei = d_in[1];
    const float* W1 = (const float*)d_in[2];
    const float* b1 = (const float*)d_in[3];
    const float* W2 = (const float*)d_in[4];
    const float* b2 = (const float*)d_in[5];
    const float* Wc = (const float*)d_in[6];
    const float* bc = (const float*)d_in[7];
    float* out = (float*)d_out;

    int n = in_sizes[0] / INF;
    int E = in_sizes[1] / 2;

    float *ph0, *ph1, *pt, *pemb;
    cudaGetSymbolAddress((void**)&ph0,  g_h0);
    cudaGetSymbolAddress((void**)&ph1,  g_h1);
    cudaGetSymbolAddress((void**)&pt,   g_t);
    cudaGetSymbolAddress((void**)&pemb, g_emb);

    int nb256 = (n + 255) / 256;
    int eb256 = (E + 255) / 256;
    int sBlk  = (n + 1023) / 1024;
    int gBlk  = (n + 127) / 128;
    int aBlk  = (n + 15) / 16;
    int fBlk  = (n + 63) / 64;

    // CSR build
    k_init <<<nb256, 256>>>((const unsigned int*)ei, n);
    k_deg  <<<eb256, 256>>>(ei, E);
    k_scan1<<<sBlk, 256>>>(n);
    k_scan2<<<1, 128>>>(sBlk);
    k_scan3<<<sBlk, 256>>>(n);
    k_place<<<eb256, 256>>>(ei, E);

    // conv1: h0 = x @ W1 (3xTF32 mma.sync)
    k_mma<INF, false><<<gBlk, 256>>>(x, W1, nullptr, ph0, n);
    k_gather<<<aBlk, 256>>>(ph0, ph1, n);

    // conv2: t = relu(h1+b1) @ W2
    k_mma<HID, true><<<gBlk, 256>>>(ph1, W2, b1, pt, n);
    k_gather<<<aBlk, 256>>>(pt, pemb, n);

    // head
    k_final<<<fBlk, 256>>>(Wc, bc, b2, out, n);
}

// round 16
// speedup vs baseline: 1.0839x; 1.0839x over previous
#include <cuda_runtime.h>
#include <cstdint>
#include <cstdio>

#define NMAX   100000
#define EMAX   1200000
#define INF    128
#define HID    64
#define OUTF   40

// ---------------- scratch (device globals) ---------------------------------
__device__ int   g_degi  [NMAX];
__device__ int   g_start [NMAX];
__device__ int   g_cursor[NMAX];
__device__ int   g_total;
__device__ float g_dinv  [NMAX];
__device__ int2  g_edge  [EMAX];        // {src, float_bits(weight)}
__device__ float g_h0    [(size_t)NMAX * HID];
__device__ float g_h1    [(size_t)NMAX * HID];
__device__ float g_t     [(size_t)NMAX * HID];
__device__ float g_emb   [(size_t)NMAX * HID];
__device__ int   g_idx64;

// ---------------- init: zero degree + dtype sniff --------------------------
__global__ void k_init(const unsigned int* __restrict__ w, int n) {
    int i = blockIdx.x * blockDim.x + threadIdx.x;
    if (i < n) g_degi[i] = 0;
    if (i == 0) g_total = 0;
    if (blockIdx.x == 0) {
        int t = threadIdx.x;
        int nz = 0;
#pragma unroll
        for (int k = 0; k < 8; k++) nz |= (w[2 * (t * 8 + k) + 1] != 0u);
        int any = __syncthreads_or(nz);
        if (t == 0) g_idx64 = (any == 0) ? 1 : 0;
    }
}

__device__ __forceinline__ void load_edge(const void* eidx, int E, int e, int& s, int& d) {
    if (g_idx64) {
        const long long* p = (const long long*)eidx;
        s = (int)p[e];
        d = (int)p[(size_t)E + e];
    } else {
        const int* p = (const int*)eidx;
        s = p[e];
        d = p[(size_t)E + e];
    }
}

__global__ void k_deg(const void* __restrict__ eidx, int E) {
    int e = blockIdx.x * blockDim.x + threadIdx.x;
    if (e >= E) return;
    int s, d;
    load_edge(eidx, E, e, s, d);
    atomicAdd(&g_degi[d], 1);
}

// ---------------- fused CSR offsets: block scan + atomic base --------------
// Range ORDER across blocks is irrelevant (per-node sums commutative), so the
// global exclusive scan is replaced by one atomicAdd of the block total.
__global__ void k_offsets(int n) {
    __shared__ int sm[256];
    __shared__ int sbase;
    int t = threadIdx.x;
    int base = blockIdx.x * 1024 + t * 4;
    int d[4];
    int s = 0;
#pragma unroll
    for (int j = 0; j < 4; j++) {
        int i = base + j;
        d[j] = (i < n) ? g_degi[i] : 0;
        s += d[j];
    }
    sm[t] = s;
    __syncthreads();
    // Hillis-Steele inclusive scan over 256 thread sums
    for (int off = 1; off < 256; off <<= 1) {
        int v = (t >= off) ? sm[t - off] : 0;
        __syncthreads();
        sm[t] += v;
        __syncthreads();
    }
    if (t == 255) sbase = atomicAdd(&g_total, sm[255]);
    __syncthreads();
    int excl = sbase + sm[t] - s;
#pragma unroll
    for (int j = 0; j < 4; j++) {
        int i = base + j;
        if (i < n) {
            g_start[i]  = excl;
            g_cursor[i] = excl;
            g_dinv[i]   = rsqrtf((float)d[j] + 1.0f);   // +1 self-loop
        }
        excl += d[j];
    }
}

__global__ void k_place(const void* __restrict__ eidx, int E) {
    int e = blockIdx.x * blockDim.x + threadIdx.x;
    if (e >= E) return;
    int s, d;
    load_edge(eidx, E, e, s, d);
    int pos = atomicAdd(&g_cursor[d], 1);
    g_edge[pos] = make_int2(s, __float_as_int(g_dinv[s] * g_dinv[d]));
}

// ---------------- GEMM: [n,KDIM] @ [KDIM,64] -> C --------------------------
// BM=128, BN=64, BK=16, 256 threads, 8x4 microtile (proven R5 version).
template <int KDIM, bool ACT>
__global__ void k_gemm64(const float* __restrict__ A, const float* __restrict__ W,
                         const float* __restrict__ actb,
                         float* __restrict__ C, int n) {
    __shared__ float xs[16][132];
    __shared__ float ws[16][64];
    const int tid = threadIdx.x;
    const int tx = tid & 15;
    const int ty = tid >> 4;
    const int rowBase = blockIdx.x * 128;

    float acc[8][4];
#pragma unroll
    for (int i = 0; i < 8; i++)
#pragma unroll
        for (int j = 0; j < 4; j++) acc[i][j] = 0.f;

    for (int k0 = 0; k0 < KDIM; k0 += 16) {
#pragma unroll
        for (int half = 0; half < 2; half++) {
            int i  = tid * 4;
            int m  = (i >> 4) + half * 64;
            int kk = i & 15;
            int row = rowBase + m;
            float4 v = make_float4(0.f, 0.f, 0.f, 0.f);
            if (row < n) {
                v = *(const float4*)&A[(size_t)row * KDIM + k0 + kk];
                if (ACT) {
                    v.x = fmaxf(v.x + actb[k0 + kk + 0], 0.f);
                    v.y = fmaxf(v.y + actb[k0 + kk + 1], 0.f);
                    v.z = fmaxf(v.z + actb[k0 + kk + 2], 0.f);
                    v.w = fmaxf(v.w + actb[k0 + kk + 3], 0.f);
                }
            }
            xs[kk + 0][m] = v.x;
            xs[kk + 1][m] = v.y;
            xs[kk + 2][m] = v.z;
            xs[kk + 3][m] = v.w;
        }
        {
            int i  = tid * 4;
            int kk = i >> 6;
            int c  = i & 63;
            *(float4*)&ws[kk][c] = *(const float4*)&W[(size_t)(k0 + kk) * 64 + c];
        }
        __syncthreads();
#pragma unroll
        for (int k = 0; k < 16; k++) {
            float4 b  = *(const float4*)&ws[k][tx * 4];
            float4 a0 = *(const float4*)&xs[k][ty * 8];
            float4 a1 = *(const float4*)&xs[k][ty * 8 + 4];
            float av[8] = {a0.x, a0.y, a0.z, a0.w, a1.x, a1.y, a1.z, a1.w};
            float bv[4] = {b.x, b.y, b.z, b.w};
#pragma unroll
            for (int i = 0; i < 8; i++)
#pragma unroll
                for (int j = 0; j < 4; j++) acc[i][j] += av[i] * bv[j];
        }
        __syncthreads();
    }

#pragma unroll
    for (int i = 0; i < 8; i++) {
        int row = rowBase + ty * 8 + i;
        if (row < n)
            *(float4*)&C[(size_t)row * 64 + tx * 4] =
                make_float4(acc[i][0], acc[i][1], acc[i][2], acc[i][3]);
    }
}

// ---------------- CSR gather aggregation -----------------------------------
__global__ void k_gather(const float* __restrict__ src, float* __restrict__ dst, int n) {
    int node = blockIdx.x * 16 + (threadIdx.x >> 4);
    int lane = threadIdx.x & 15;
    if (node >= n) return;

    const float4* s4 = (const float4*)src;
    float di = g_dinv[node];
    float4 a = s4[(size_t)node * 16 + lane];
    float w0 = di * di;
    float4 acc = make_float4(a.x * w0, a.y * w0, a.z * w0, a.w * w0);

    int e   = g_start[node];
    int end = e + g_degi[node];

    for (; e + 4 <= end; e += 4) {
        int2 e0 = g_edge[e],     e1 = g_edge[e + 1];
        int2 e2 = g_edge[e + 2], e3 = g_edge[e + 3];
        float w0_ = __int_as_float(e0.y), w1_ = __int_as_float(e1.y);
        float w2_ = __int_as_float(e2.y), w3_ = __int_as_float(e3.y);
        float4 v0 = s4[(size_t)e0.x * 16 + lane];
        float4 v1 = s4[(size_t)e1.x * 16 + lane];
        float4 v2 = s4[(size_t)e2.x * 16 + lane];
        float4 v3 = s4[(size_t)e3.x * 16 + lane];
        acc.x += w0_ * v0.x + w1_ * v1.x + w2_ * v2.x + w3_ * v3.x;
        acc.y += w0_ * v0.y + w1_ * v1.y + w2_ * v2.y + w3_ * v3.y;
        acc.z += w0_ * v0.z + w1_ * v1.z + w2_ * v2.z + w3_ * v3.z;
        acc.w += w0_ * v0.w + w1_ * v1.w + w2_ * v2.w + w3_ * v3.w;
    }
    for (; e < end; e++) {
        int2 ee = g_edge[e];
        float w_ = __int_as_float(ee.y);
        float4 v0 = s4[(size_t)ee.x * 16 + lane];
        acc.x += w_ * v0.x; acc.y += w_ * v0.y; acc.z += w_ * v0.z; acc.w += w_ * v0.w;
    }
    ((float4*)dst)[(size_t)node * 16 + lane] = acc;
}

// ---------------- final head: emb+b2, logits, softmax, argmax --------------
__global__ void k_final(const float* __restrict__ Wc, const float* __restrict__ bc,
                        const float* __restrict__ b2,
                        float* __restrict__ out, int n) {
    __shared__ float Wcs[64][40];
    __shared__ float embs[64][65];
    __shared__ float lg[64][41];
    __shared__ float bcs[40];
    __shared__ float b2s[64];
    __shared__ float rsum[64];

    int tid  = threadIdx.x;
    int base = blockIdx.x * 64;

    for (int i = tid; i < 64 * 40; i += 256) Wcs[i / 40][i % 40] = Wc[i];
    if (tid < 40) bcs[tid] = bc[tid];
    if (tid < 64) b2s[tid] = b2[tid];
    __syncthreads();

    float* outL = out;
    float* outE = out + (size_t)n * 40;
    float* outS = out + (size_t)n * 104;
    float* outH = out + (size_t)n * 144;

    for (int i = tid; i < 64 * 64; i += 256) {
        int r = i >> 6, c = i & 63;
        int node = base + r;
        float v = 0.f;
        if (node < n) {
            v = g_emb[(size_t)node * 64 + c] + b2s[c];
            outE[(size_t)node * 64 + c] = v;
        }
        embs[r][c] = v;
    }
    __syncthreads();

    int tx = tid & 7, ty = tid >> 3;
    float acc[2][5];
#pragma unroll
    for (int i = 0; i < 2; i++)
#pragma unroll
        for (int j = 0; j < 5; j++) acc[i][j] = bcs[tx * 5 + j];
    for (int k = 0; k < 64; k++) {
        float a0 = embs[ty * 2 + 0][k];
        float a1 = embs[ty * 2 + 1][k];
#pragma unroll
        for (int j = 0; j < 5; j++) {
            float b = Wcs[k][tx * 5 + j];
            acc[0][j] += a0 * b;
            acc[1][j] += a1 * b;
        }
    }
#pragma unroll
    for (int i = 0; i < 2; i++)
#pragma unroll
        for (int j = 0; j < 5; j++) lg[ty * 2 + i][tx * 5 + j] = acc[i][j];
    __syncthreads();

    for (int i = tid; i < 64 * 40; i += 256) {
        int r = i / 40, c = i % 40;
        int node = base + r;
        if (node < n) outL[(size_t)node * 40 + c] = lg[r][c];
    }
    __syncthreads();

    if (tid < 64) {
        int node = base + tid;
        float m = -1e30f;
        int bi = 0;
#pragma unroll
        for (int j = 0; j < 40; j++) {
            float v = lg[tid][j];
            if (v > m) { m = v; bi = j; }
        }
        float s = 0.f;
#pragma unroll
        for (int j = 0; j < 40; j++) {
            float e = __expf(lg[tid][j] - m);
            lg[tid][j] = e;
            s += e;
        }
        rsum[tid] = 1.f / s;
        if (node < n) outH[node] = (float)bi;
    }
    __syncthreads();

    for (int i = tid; i < 64 * 40; i += 256) {
        int r = i / 40, c = i % 40;
        int node = base + r;
        if (node < n) outS[(size_t)node * 40 + c] = lg[r][c] * rsum[r];
    }
}

// ---------------- launch ----------------------------------------------------
extern "C" void kernel_launch(void* const* d_in, const int* in_sizes, int n_in,
                              void* d_out, int out_size) {
    const float* x  = (const float*)d_in[0];
    const void*  ei = d_in[1];
    const float* W1 = (const float*)d_in[2];
    const float* b1 = (const float*)d_in[3];
    const float* W2 = (const float*)d_in[4];
    const float* b2 = (const float*)d_in[5];
    const float* Wc = (const float*)d_in[6];
    const float* bc = (const float*)d_in[7];
    float* out = (float*)d_out;

    int n = in_sizes[0] / INF;
    int E = in_sizes[1] / 2;

    float *ph0, *ph1, *pt, *pemb;
    cudaGetSymbolAddress((void**)&ph0,  g_h0);
    cudaGetSymbolAddress((void**)&ph1,  g_h1);
    cudaGetSymbolAddress((void**)&pt,   g_t);
    cudaGetSymbolAddress((void**)&pemb, g_emb);

    int nb256 = (n + 255) / 256;
    int eb256 = (E + 255) / 256;
    int sBlk  = (n + 1023) / 1024;
    int gBlk  = (n + 127) / 128;
    int aBlk  = (n + 15) / 16;
    int fBlk  = (n + 63) / 64;

    // Side stream + fork/join events (created fresh per call; kernel_launch is
    // invoked only a handful of times — correctness + capture — never per replay).
    cudaStream_t s1;
    cudaStreamCreateWithFlags(&s1, cudaStreamNonBlocking);
    cudaEvent_t evF, evJ;
    cudaEventCreateWithFlags(&evF, cudaEventDisableTiming);
    cudaEventCreateWithFlags(&evJ, cudaEventDisableTiming);

    // Fork: GEMM1 (x@W1) is independent of the CSR build — run it on s1.
    cudaEventRecord(evF, 0);
    cudaStreamWaitEvent(s1, evF, 0);
    k_gemm64<INF, false><<<gBlk, 256, 0, s1>>>(x, W1, nullptr, ph0, n);

    // CSR build on the main (captured) stream, overlapped with GEMM1.
    k_init   <<<nb256, 256>>>((const unsigned int*)ei, n);
    k_deg    <<<eb256, 256>>>(ei, E);
    k_offsets<<<sBlk, 256>>>(n);
    k_place  <<<eb256, 256>>>(ei, E);

    // Join: gather1 needs both GEMM1 output and the CSR.
    cudaEventRecord(evJ, s1);
    cudaStreamWaitEvent(0, evJ, 0);

    k_gather<<<aBlk, 256>>>(ph0, ph1, n);

    // conv2: t = relu(h1+b1) @ W2, then aggregate
    k_gemm64<HID, true><<<gBlk, 256>>>(ph1, W2, b1, pt, n);
    k_gather<<<aBlk, 256>>>(pt, pemb, n);

    // head
    k_final<<<fBlk, 256>>>(Wc, bc, b2, out, n);
}